// round 15
// baseline (speedup 1.0000x reference)
#include <cuda_runtime.h>
#include <math.h>
#include <float.h>

#define G    1024
#define KNN  8

typedef unsigned long long u64;

// ---------------- scratch (static device globals: no allocation) ----------------
__device__ float g_trk[G*64*128];
__device__ float g_U2 [G*64*128];
__device__ float g_Wd1[128*128];   // Wc1_top - Wc1_bot
__device__ float g_Wd2[128*128];   // Wc2_top - Wc2_bot

__device__ __forceinline__ float eluf(float x) { return x > 0.f ? x : expm1f(x); }

// ---- packed f32x2 helpers ----
__device__ __forceinline__ u64 splat2(float a) {
    u64 r; asm("mov.b64 %0, {%1, %1};" : "=l"(r) : "f"(a)); return r;
}
__device__ __forceinline__ u64 pack2f(float x, float y) {
    u64 r; asm("mov.b64 %0, {%1, %2};" : "=l"(r) : "f"(x), "f"(y)); return r;
}
__device__ __forceinline__ void ffma2(u64& c, u64 a, u64 b) {
    asm("fma.rn.f32x2 %0, %1, %2, %0;" : "+l"(c) : "l"(a), "l"(b));
}
__device__ __forceinline__ float2 unpack2(u64 v) {
    float2 f; asm("mov.b64 {%0, %1}, %2;" : "=f"(f.x), "=f"(f.y) : "l"(v)); return f;
}

// ---- 32x128 weight chunk staging ----
__device__ __forceinline__ void stage256(float* dst, const float* __restrict__ W,
                                         int kc, int tid)
{
    #pragma unroll
    for (int e = 0; e < 4; e++)
        ((float4*)dst)[tid + e * 256] = ((const float4*)W)[kc * 1024 + tid + e * 256];
}
__device__ __forceinline__ void stage512(float* dst, const float* __restrict__ W,
                                         int kc, int tid)
{
    #pragma unroll
    for (int e = 0; e < 2; e++)
        ((float4*)dst)[tid + e * 512] = ((const float4*)W)[kc * 1024 + tid + e * 512];
}

// ---- GEMM core over one 32-k chunk, 256 threads, 8x8 microtile (trk kernel) ----
__device__ __forceinline__ void zero_acc8(u64 acc[8][4]) {
    #pragma unroll
    for (int i = 0; i < 8; i++)
        #pragma unroll
        for (int j = 0; j < 4; j++) acc[i][j] = 0ull;
}
__device__ __forceinline__ void gemm_chunk(const float* __restrict__ Hs,
                                           const float* __restrict__ Ws,
                                           u64 acc[8][4], int tx, int ty)
{
    #pragma unroll 4
    for (int kk = 0; kk < 32; kk++) {
        const float* arow = &Hs[kk * 132 + ty * 8];
        float4 a0 = *(const float4*)arow;
        float4 a1 = *(const float4*)(arow + 4);
        const u64* br = (const u64*)&Ws[kk * 128];
        u64 b0 = br[tx], b1 = br[tx + 16], b2 = br[tx + 32], b3 = br[tx + 48];
        u64 s;
        s = splat2(a0.x); ffma2(acc[0][0],s,b0); ffma2(acc[0][1],s,b1); ffma2(acc[0][2],s,b2); ffma2(acc[0][3],s,b3);
        s = splat2(a0.y); ffma2(acc[1][0],s,b0); ffma2(acc[1][1],s,b1); ffma2(acc[1][2],s,b2); ffma2(acc[1][3],s,b3);
        s = splat2(a0.z); ffma2(acc[2][0],s,b0); ffma2(acc[2][1],s,b1); ffma2(acc[2][2],s,b2); ffma2(acc[2][3],s,b3);
        s = splat2(a0.w); ffma2(acc[3][0],s,b0); ffma2(acc[3][1],s,b1); ffma2(acc[3][2],s,b2); ffma2(acc[3][3],s,b3);
        s = splat2(a1.x); ffma2(acc[4][0],s,b0); ffma2(acc[4][1],s,b1); ffma2(acc[4][2],s,b2); ffma2(acc[4][3],s,b3);
        s = splat2(a1.y); ffma2(acc[5][0],s,b0); ffma2(acc[5][1],s,b1); ffma2(acc[5][2],s,b2); ffma2(acc[5][3],s,b3);
        s = splat2(a1.z); ffma2(acc[6][0],s,b0); ffma2(acc[6][1],s,b1); ffma2(acc[6][2],s,b2); ffma2(acc[6][3],s,b3);
        s = splat2(a1.w); ffma2(acc[7][0],s,b0); ffma2(acc[7][1],s,b1); ffma2(acc[7][2],s,b2); ffma2(acc[7][3],s,b3);
    }
}
__device__ __forceinline__ void gemm_pass(const float* __restrict__ Hs, float* Wb,
                                          const float* __restrict__ W,
                                          u64 acc[8][4], int tid, int tx, int ty)
{
    stage256(Wb, W, 0, tid);
    __syncthreads();
    #pragma unroll
    for (int kc = 0; kc < 4; kc++) {
        if (kc < 3) stage256(Wb + ((kc + 1) & 1) * 4096, W, kc + 1, tid);
        gemm_chunk(Hs + kc * 32 * 132, Wb + (kc & 1) * 4096, acc, tx, ty);
        __syncthreads();
    }
}
__device__ __forceinline__ void store256w(const u64 acc[8][4], float* __restrict__ C,
                                          size_t row0, int tx, int ty)
{
    #pragma unroll
    for (int ii = 0; ii < 8; ii++) {
        size_t r = row0 + ty * 8 + ii;
        #pragma unroll
        for (int j = 0; j < 4; j++) {
            float2 p = unpack2(acc[ii][j]);
            *(float2*)&C[r * 128 + tx * 2 + j * 32] = p;
        }
    }
}

// ---------------- diff-weight precompute ----------------
__global__ __launch_bounds__(256)
void diff_kernel(const float* __restrict__ Wc1, const float* __restrict__ Wc2,
                 float* __restrict__ D1, float* __restrict__ D2)
{
    int i = blockIdx.x * 256 + threadIdx.x;
    D1[i] = Wc1[i] - Wc1[i + 16384];
    D2[i] = Wc2[i] - Wc2[i + 16384];
}

// =====================================================================
// trk node kernel (unchanged): layer1 -> feats -> trkF + U2
// =====================================================================
__global__ __launch_bounds__(256, 2)
void trk_kernel(const float* __restrict__ X,
                const float* __restrict__ W1, const float* __restrict__ b1,
                const float* __restrict__ W2, const float* __restrict__ b2,
                const float* __restrict__ Wd2,
                float* __restrict__ Yf, float* __restrict__ Yu2)
{
    extern __shared__ float sm[];
    float* Hs  = sm;                    // 128*132
    float* Wb  = Hs + 16896;            // 2*4096
    float* Xin = Wb + 8192;             // 1024
    float* W1s = Xin + 1024;            // 1024
    float* b1s = W1s + 1024;            // 128
    const int tid = threadIdx.x;
    const int tx = tid & 15, ty = tid >> 4;
    const size_t row0 = (size_t)blockIdx.x * 128;

    for (int t = tid; t < 1024; t += 256) Xin[t] = X[row0 * 8 + t];
    for (int t = tid; t < 1024; t += 256) W1s[t] = W1[t];
    if (tid < 128) b1s[tid] = b1[tid];
    __syncthreads();

    {
        int r = tid >> 1, ch = (tid & 1) * 64;
        float xr[8];
        #pragma unroll
        for (int d = 0; d < 8; d++) xr[d] = Xin[r * 8 + d];
        #pragma unroll 4
        for (int cc = 0; cc < 64; cc++) {
            int c = ch + cc;
            float a = b1s[c];
            #pragma unroll
            for (int d = 0; d < 8; d++) a = fmaf(xr[d], W1s[d * 128 + c], a);
            Hs[c * 132 + r] = eluf(a);
        }
    }

    u64 acc[8][4];
    zero_acc8(acc);
    gemm_pass(Hs, Wb, W2, acc, tid, tx, ty);

    {
        float2 bv[4];
        #pragma unroll
        for (int j = 0; j < 4; j++) bv[j] = *(const float2*)&b2[tx * 2 + j * 32];
        #pragma unroll
        for (int ii = 0; ii < 8; ii++) {
            int rr = ty * 8 + ii;
            #pragma unroll
            for (int j = 0; j < 4; j++) {
                float2 p = unpack2(acc[ii][j]);
                float va = fmaxf(p.x + bv[j].x, 0.f);
                float vb = fmaxf(p.y + bv[j].y, 0.f);
                int c = tx * 2 + j * 32;
                float2 o = {va, vb};
                *(float2*)&Yf[(row0 + rr) * 128 + c] = o;
                Hs[c * 132 + rr]       = va;
                Hs[(c + 1) * 132 + rr] = vb;
            }
        }
    }
    __syncthreads();

    zero_acc8(acc);
    gemm_pass(Hs, Wb, Wd2, acc, tid, tx, ty);
    store256w(acc, Yu2, row0, tx, ty);
}

// =====================================================================
// MERGED convs kernel: conv1 (sv MLP + V1 + U1) + conv2 (V2) + head.
// One block per graph, 512 threads, ~106.5KB smem -> 2 blocks/SM.
// f1 never touches DRAM; trk tile loaded once.
// =====================================================================
__global__ __launch_bounds__(512, 2)
void convs_kernel(const float* __restrict__ trkF, const float* __restrict__ x_sv,
                  const float* __restrict__ Wsv1, const float* __restrict__ bsv1,
                  const float* __restrict__ Wsv2, const float* __restrict__ bsv2,
                  const float* __restrict__ Wd1,  const float* __restrict__ bc1g,
                  const float* __restrict__ Wbot1,
                  const float* __restrict__ U2,   const float* __restrict__ Wbot2,
                  const float* __restrict__ bc2,
                  const float* __restrict__ Wo1, const float* __restrict__ bo1,
                  const float* __restrict__ Wo2, const float* __restrict__ bo2,
                  const float* __restrict__ Wo3, const float* __restrict__ bo3,
                  const float* __restrict__ Wo4, const float* __restrict__ bo4,
                  float* __restrict__ out, int out_size)
{
    extern __shared__ float sm[];
    float* dsh = sm;                    // 8448: trk; later V2
    float* fsh = dsh + 8448;            // 8448: U1 staging, then f1
    float* svh = fsh + 8448;            // 2112: sv hidden; later V1
    float* s2h = svh + 2112;            // 2112: sv feats
    float* sc  = s2h + 2112;            // 4160: scores (64x65 / 64x17); aliased W chunk buf (4096)
    float* sn2 = sc + 4160;             // 64
    float* colsum = sn2 + 64;           // 512
    float* pooled = colsum + 512;       // 128
    float* h1 = pooled + 128;           // 64
    float* h2 = h1 + 64;                // 32
    float* h3 = h2 + 32;                // 4
    float* S  = h3 + 4;                 // 672 smalls
    int* idxs = (int*)(S + 672);        // 512 ints

    float* xsv = S;          // 32
    float* w1  = S + 32;     // 256
    float* b1s = S + 288;    // 128
    float* b2s = S + 416;    // 128
    float* bc1 = S + 544;    // 128

    const int tid  = threadIdx.x;
    const int lane = tid & 31, wid = tid >> 5;   // 16 warps
    const int tx   = tid & 15, ty = tid >> 4;    // ty: 0..31
    const int g    = blockIdx.x;
    const float* dg = trkF + (size_t)g * 64 * 128;
    const float* Ug = U2   + (size_t)g * 64 * 128;

    // ---- P0: load trk tile + smalls ----
    for (int t = tid; t < 64 * 128; t += 512)
        dsh[(t >> 7) * 132 + (t & 127)] = dg[t];
    if (tid < 32)  xsv[tid] = x_sv[g * 32 + tid];
    if (tid < 256) w1[tid] = Wsv1[tid];
    if (tid < 128) { b1s[tid] = bsv1[tid]; b2s[tid] = bsv2[tid]; bc1[tid] = bc1g[tid]; }
    __syncthreads();

    // ---- P1: sv layer1 -> svh (16 x 128, ld 132) ----
    {
        int r = tid >> 5, c4 = lane * 4;
        float x0 = xsv[r * 2], x1 = xsv[r * 2 + 1];
        #pragma unroll
        for (int q = 0; q < 4; q++) {
            int c = c4 + q;
            svh[r * 132 + c] = eluf(b1s[c] + x0 * w1[c] + x1 * w1[128 + c]);
        }
    }
    __syncthreads();

    // ---- P2: sv layer2 (stream Wsv2 via sc) -> s2h = relu ----
    {
        u64 a[2] = {0ull, 0ull};
        int r = tid >> 5, cu0 = lane, cu1 = lane + 32;
        for (int kc = 0; kc < 4; kc++) {
            stage512(sc, Wsv2, kc, tid);
            __syncthreads();
            #pragma unroll 2
            for (int k4 = 0; k4 < 32; k4 += 4) {
                float4 sv4 = *(const float4*)&svh[r * 132 + kc * 32 + k4];
                #pragma unroll
                for (int q = 0; q < 4; q++) {
                    float el = (q == 0) ? sv4.x : (q == 1) ? sv4.y : (q == 2) ? sv4.z : sv4.w;
                    u64 s = splat2(el);
                    const u64* br = (const u64*)&sc[(k4 + q) * 128];
                    ffma2(a[0], s, br[cu0]);
                    ffma2(a[1], s, br[cu1]);
                }
            }
            __syncthreads();
        }
        float2 p0 = unpack2(a[0]), p1 = unpack2(a[1]);
        int c0 = 2 * cu0, c1 = 2 * cu1;
        s2h[r * 132 + c0]     = fmaxf(p0.x + b2s[c0],     0.f);
        s2h[r * 132 + c0 + 1] = fmaxf(p0.y + b2s[c0 + 1], 0.f);
        s2h[r * 132 + c1]     = fmaxf(p1.x + b2s[c1],     0.f);
        s2h[r * 132 + c1 + 1] = fmaxf(p1.y + b2s[c1 + 1], 0.f);
    }
    __syncthreads();

    // ---- P3: sv norms (16 warps x 1 row) ----
    {
        const float* rp = &s2h[wid * 132];
        float e0 = rp[lane], e1 = rp[32 + lane], e2 = rp[64 + lane], e3 = rp[96 + lane];
        float s = e0*e0 + e1*e1 + e2*e2 + e3*e3;
        #pragma unroll
        for (int off = 16; off > 0; off >>= 1) s += __shfl_xor_sync(~0u, s, off);
        if (lane == 0) sn2[wid] = s;
    }
    __syncthreads();

    // ---- P4: scores1 (64 x 16): i = tid>>3, cols jj & jj+8 ----
    {
        int i = tid >> 3, jj = tid & 7;
        u64 a0 = 0ull, a1 = 0ull;
        #pragma unroll 4
        for (int k4 = 0; k4 < 128; k4 += 4) {
            float4 av = *(const float4*)&dsh[i * 132 + k4];
            u64 ap = pack2f(av.x, av.y), aq = pack2f(av.z, av.w);
            float4 b0 = *(const float4*)&s2h[jj * 132 + k4];
            float4 b1 = *(const float4*)&s2h[(jj + 8) * 132 + k4];
            ffma2(a0, ap, pack2f(b0.x, b0.y)); ffma2(a0, aq, pack2f(b0.z, b0.w));
            ffma2(a1, ap, pack2f(b1.x, b1.y)); ffma2(a1, aq, pack2f(b1.z, b1.w));
        }
        float2 p = unpack2(a0);
        sc[i * 17 + jj]     = sn2[jj]     - 2.f * (p.x + p.y);
        p = unpack2(a1);
        sc[i * 17 + jj + 8] = sn2[jj + 8] - 2.f * (p.x + p.y);
    }
    __syncthreads();

    // ---- P5: topk1 (16 warps x 4 rows, 16 cands, tie -> lowest idx) ----
    #pragma unroll
    for (int q = 0; q < 4; q++) {
        int row = wid * 4 + q;
        float mv = (lane < 16) ? sc[row * 17 + lane] : FLT_MAX;
        #pragma unroll
        for (int n = 0; n < KNN; n++) {
            float cv = mv; int ci = lane;
            #pragma unroll
            for (int off = 16; off > 0; off >>= 1) {
                float ov = __shfl_xor_sync(~0u, cv, off);
                int   oi = __shfl_xor_sync(~0u, ci, off);
                if (ov < cv || (ov == cv && oi < ci)) { cv = ov; ci = oi; }
            }
            if (lane == 0) idxs[row * 8 + n] = ci;
            if (lane == ci) mv = FLT_MAX;
        }
    }
    __syncthreads();   // scores1 dead -> sc usable as W chunk buf

    // ---- P6: U1 = trk @ Wd1 -> fsh (raw) ----
    {
        u64 accv[2][4];
        #pragma unroll
        for (int a = 0; a < 2; a++)
            #pragma unroll
            for (int b = 0; b < 4; b++) accv[a][b] = 0ull;
        const int r0 = 2 * ty, r1 = 2 * ty + 1;
        for (int kc = 0; kc < 4; kc++) {
            stage512(sc, Wd1, kc, tid);
            __syncthreads();
            #pragma unroll 2
            for (int k4 = 0; k4 < 32; k4 += 4) {
                float4 s0v = *(const float4*)&dsh[r0 * 132 + kc * 32 + k4];
                float4 s1v = *(const float4*)&dsh[r1 * 132 + kc * 32 + k4];
                #pragma unroll
                for (int q = 0; q < 4; q++) {
                    float e0 = (q == 0) ? s0v.x : (q == 1) ? s0v.y : (q == 2) ? s0v.z : s0v.w;
                    float e1 = (q == 0) ? s1v.x : (q == 1) ? s1v.y : (q == 2) ? s1v.z : s1v.w;
                    u64 s0 = splat2(e0), s1 = splat2(e1);
                    const u64* br = (const u64*)&sc[(k4 + q) * 128];
                    u64 b0 = br[tx], b1 = br[tx + 16], b2 = br[tx + 32], b3 = br[tx + 48];
                    ffma2(accv[0][0],s0,b0); ffma2(accv[0][1],s0,b1); ffma2(accv[0][2],s0,b2); ffma2(accv[0][3],s0,b3);
                    ffma2(accv[1][0],s1,b0); ffma2(accv[1][1],s1,b1); ffma2(accv[1][2],s1,b2); ffma2(accv[1][3],s1,b3);
                }
            }
            __syncthreads();
        }
        #pragma unroll
        for (int ii = 0; ii < 2; ii++) {
            int r = 2 * ty + ii;
            #pragma unroll
            for (int j = 0; j < 4; j++) {
                float2 p = unpack2(accv[ii][j]);
                *(float2*)&fsh[r * 132 + 2 * tx + 32 * j] = p;
            }
        }
    }
    __syncthreads();

    // ---- P7: V1 = svfeat @ Wbot1 -> svh (hidden dead) ----
    {
        u64 a[2] = {0ull, 0ull};
        int r = tid >> 5, cu0 = lane, cu1 = lane + 32;
        for (int kc = 0; kc < 4; kc++) {
            stage512(sc, Wbot1, kc, tid);
            __syncthreads();
            #pragma unroll 2
            for (int k4 = 0; k4 < 32; k4 += 4) {
                float4 sv4 = *(const float4*)&s2h[r * 132 + kc * 32 + k4];
                #pragma unroll
                for (int q = 0; q < 4; q++) {
                    float el = (q == 0) ? sv4.x : (q == 1) ? sv4.y : (q == 2) ? sv4.z : sv4.w;
                    u64 s = splat2(el);
                    const u64* br = (const u64*)&sc[(k4 + q) * 128];
                    ffma2(a[0], s, br[cu0]);
                    ffma2(a[1], s, br[cu1]);
                }
            }
            __syncthreads();
        }
        float2 p0 = unpack2(a[0]), p1 = unpack2(a[1]);
        *(float2*)&svh[r * 132 + 2 * cu0] = p0;
        *(float2*)&svh[r * 132 + 2 * cu1] = p1;
    }
    __syncthreads();

    // ---- P8: combine1 -> fsh = f1 = elu(U1 + bc1 + max_n V1[idx]) ----
    #pragma unroll
    for (int ii = 0; ii < 2; ii++) {
        int row = 2 * ty + ii;
        const int* ip = &idxs[row * 8];
        #pragma unroll
        for (int j = 0; j < 4; j++) {
            int c = 2 * tx + 32 * j;
            float mx = -FLT_MAX, my = -FLT_MAX;
            #pragma unroll
            for (int n = 0; n < KNN; n++) {
                float2 v = *(const float2*)&svh[ip[n] * 132 + c];
                mx = fmaxf(mx, v.x); my = fmaxf(my, v.y);
            }
            float2 u = *(const float2*)&fsh[row * 132 + c];
            float2 o = { eluf(u.x + bc1[c] + mx), eluf(u.y + bc1[c + 1] + my) };
            *(float2*)&fsh[row * 132 + c] = o;
        }
    }
    __syncthreads();

    // ================= conv2 phases =================

    // ---- P9: f1 norms (16 warps x 4 rows) ----
    #pragma unroll
    for (int q = 0; q < 4; q++) {
        int row = wid * 4 + q;
        const float* rp = &fsh[row * 132];
        float e0 = rp[lane], e1 = rp[32 + lane], e2 = rp[64 + lane], e3 = rp[96 + lane];
        float s = e0*e0 + e1*e1 + e2*e2 + e3*e3;
        #pragma unroll
        for (int off = 16; off > 0; off >>= 1) s += __shfl_xor_sync(~0u, s, off);
        if (lane == 0) sn2[row] = s;
    }
    __syncthreads();

    // ---- P10: scores2 (64 x 64) ----
    {
        u64 acc[2][4];
        #pragma unroll
        for (int a = 0; a < 2; a++)
            #pragma unroll
            for (int b = 0; b < 4; b++) acc[a][b] = 0ull;
        const int r0 = 2 * ty, r1 = 2 * ty + 1;
        #pragma unroll 4
        for (int k4 = 0; k4 < 128; k4 += 4) {
            float4 av0 = *(const float4*)&dsh[r0 * 132 + k4];
            float4 av1 = *(const float4*)&dsh[r1 * 132 + k4];
            u64 a0p = pack2f(av0.x, av0.y), a0q = pack2f(av0.z, av0.w);
            u64 a1p = pack2f(av1.x, av1.y), a1q = pack2f(av1.z, av1.w);
            #pragma unroll
            for (int jj = 0; jj < 4; jj++) {
                float4 bv = *(const float4*)&fsh[(tx + jj * 16) * 132 + k4];
                u64 bp = pack2f(bv.x, bv.y), bq = pack2f(bv.z, bv.w);
                ffma2(acc[0][jj], a0p, bp); ffma2(acc[0][jj], a0q, bq);
                ffma2(acc[1][jj], a1p, bp); ffma2(acc[1][jj], a1q, bq);
            }
        }
        #pragma unroll
        for (int ii = 0; ii < 2; ii++)
            #pragma unroll
            for (int jj = 0; jj < 4; jj++) {
                float2 p = unpack2(acc[ii][jj]);
                int j = tx + jj * 16;
                sc[(ty * 2 + ii) * 65 + j] = sn2[j] - 2.f * (p.x + p.y);
            }
    }
    __syncthreads();

    // ---- P11: topk2 (64 candidates, 2 per lane) ----
    #pragma unroll
    for (int q = 0; q < 4; q++) {
        int row = wid * 4 + q;
        float v0 = sc[row * 65 + lane];
        float v1 = sc[row * 65 + 32 + lane];
        #pragma unroll
        for (int n = 0; n < KNN; n++) {
            float cv; int ci;
            if (v1 < v0) { cv = v1; ci = lane + 32; }
            else         { cv = v0; ci = lane; }
            #pragma unroll
            for (int off = 16; off > 0; off >>= 1) {
                float ov = __shfl_xor_sync(~0u, cv, off);
                int   oi = __shfl_xor_sync(~0u, ci, off);
                if (ov < cv || (ov == cv && oi < ci)) { cv = ov; ci = oi; }
            }
            if (lane == 0) idxs[row * 8 + n] = ci;
            if (ci == lane)           v0 = FLT_MAX;
            else if (ci == lane + 32) v1 = FLT_MAX;
        }
    }
    __syncthreads();   // sc free again; trk (dsh) dead

    // ---- P12: V2 = f1 @ Wbot2 -> dsh ----
    {
        u64 accv[2][4];
        #pragma unroll
        for (int a = 0; a < 2; a++)
            #pragma unroll
            for (int b = 0; b < 4; b++) accv[a][b] = 0ull;
        const int r0 = 2 * ty, r1 = 2 * ty + 1;
        for (int kc = 0; kc < 4; kc++) {
            stage512(sc, Wbot2, kc, tid);
            __syncthreads();
            #pragma unroll 2
            for (int k4 = 0; k4 < 32; k4 += 4) {
                float4 s0v = *(const float4*)&fsh[r0 * 132 + kc * 32 + k4];
                float4 s1v = *(const float4*)&fsh[r1 * 132 + kc * 32 + k4];
                #pragma unroll
                for (int q = 0; q < 4; q++) {
                    float e0 = (q == 0) ? s0v.x : (q == 1) ? s0v.y : (q == 2) ? s0v.z : s0v.w;
                    float e1 = (q == 0) ? s1v.x : (q == 1) ? s1v.y : (q == 2) ? s1v.z : s1v.w;
                    u64 s0 = splat2(e0), s1 = splat2(e1);
                    const u64* br = (const u64*)&sc[(k4 + q) * 128];
                    u64 b0 = br[tx], b1 = br[tx + 16], b2 = br[tx + 32], b3 = br[tx + 48];
                    ffma2(accv[0][0],s0,b0); ffma2(accv[0][1],s0,b1); ffma2(accv[0][2],s0,b2); ffma2(accv[0][3],s0,b3);
                    ffma2(accv[1][0],s1,b0); ffma2(accv[1][1],s1,b1); ffma2(accv[1][2],s1,b2); ffma2(accv[1][3],s1,b3);
                }
            }
            __syncthreads();
        }
        #pragma unroll
        for (int ii = 0; ii < 2; ii++) {
            int r = 2 * ty + ii;
            #pragma unroll
            for (int j = 0; j < 4; j++) {
                float2 p = unpack2(accv[ii][j]);
                *(float2*)&dsh[r * 132 + 2 * tx + 32 * j] = p;
            }
        }
    }
    __syncthreads();

    // ---- P13: combine2 + column sums ----
    {
        int c = tid & 127, ih = tid >> 7;
        float bc = bc2[c];
        float csum = 0.f;
        #pragma unroll 4
        for (int i0 = 0; i0 < 64; i0 += 4) {
            int i = i0 + ih;
            const int* ip = &idxs[i * 8];
            float vmax = -FLT_MAX;
            #pragma unroll
            for (int n = 0; n < KNN; n++) vmax = fmaxf(vmax, dsh[ip[n] * 132 + c]);
            csum += eluf(Ug[i * 128 + c] + bc + vmax);
        }
        colsum[ih * 128 + c] = csum;
    }
    __syncthreads();

    // ---- P14: pooled mean + head ----
    if (tid < 128)
        pooled[tid] = (colsum[tid] + colsum[128 + tid] + colsum[256 + tid] + colsum[384 + tid]) * (1.f / 64.f);
    __syncthreads();
    if (tid < 64) {
        float a = bo1[tid];
        #pragma unroll 8
        for (int d = 0; d < 128; d++) a += pooled[d] * Wo1[d * 64 + tid];
        h1[tid] = eluf(a);
    }
    __syncthreads();
    if (tid < 32) {
        float a = bo2[tid];
        #pragma unroll 8
        for (int d = 0; d < 64; d++) a += h1[d] * Wo2[d * 32 + tid];
        h2[tid] = eluf(a);
    }
    __syncthreads();
    if (tid < 4) {
        float a = bo3[tid];
        #pragma unroll
        for (int d = 0; d < 32; d++) a += h2[d] * Wo3[d * 4 + tid];
        h3[tid] = eluf(a);
    }
    __syncthreads();
    if (tid == 0) {
        float a = bo4[0];
        #pragma unroll
        for (int d = 0; d < 4; d++) a += h3[d] * Wo4[d];
        out[g] = a;
        if (out_size >= 2 * G) out[G + g] = (float)g;
    }
}

// ---------------- launch ----------------
extern "C" void kernel_launch(void* const* d_in, const int* in_sizes, int n_in,
                              void* d_out, int out_size)
{
    const float* x_sv   = (const float*)d_in[0];
    const float* x_trk  = (const float*)d_in[1];
    const float* W_sv1  = (const float*)d_in[2];
    const float* b_sv1  = (const float*)d_in[3];
    const float* W_sv2  = (const float*)d_in[4];
    const float* b_sv2  = (const float*)d_in[5];
    const float* W_trk1 = (const float*)d_in[6];
    const float* b_trk1 = (const float*)d_in[7];
    const float* W_trk2 = (const float*)d_in[8];
    const float* b_trk2 = (const float*)d_in[9];
    const float* W_c1   = (const float*)d_in[10];
    const float* b_c1   = (const float*)d_in[11];
    const float* W_c2   = (const float*)d_in[12];
    const float* b_c2   = (const float*)d_in[13];
    const float* W_o1   = (const float*)d_in[14];
    const float* b_o1   = (const float*)d_in[15];
    const float* W_o2   = (const float*)d_in[16];
    const float* b_o2   = (const float*)d_in[17];
    const float* W_o3   = (const float*)d_in[18];
    const float* b_o3   = (const float*)d_in[19];
    const float* W_o4   = (const float*)d_in[20];
    const float* b_o4   = (const float*)d_in[21];
    float* out = (float*)d_out;

    float *p_trk, *p_U2, *p_Wd1, *p_Wd2;
    cudaGetSymbolAddress((void**)&p_trk, g_trk);
    cudaGetSymbolAddress((void**)&p_U2,  g_U2);
    cudaGetSymbolAddress((void**)&p_Wd1, g_Wd1);
    cudaGetSymbolAddress((void**)&p_Wd2, g_Wd2);

    const int smem_b = (16896 + 8192 + 1024 + 1024 + 128) * 4;
    const int smem_m = (8448 + 8448 + 2112 + 2112 + 4160 + 64 + 512 + 128
                        + 64 + 32 + 4 + 672) * 4 + 512 * 4;

    (void)cudaFuncSetAttribute(trk_kernel,   cudaFuncAttributeMaxDynamicSharedMemorySize, smem_b);
    (void)cudaFuncSetAttribute(convs_kernel, cudaFuncAttributeMaxDynamicSharedMemorySize, smem_m);

    // 0: diff weights
    diff_kernel<<<64, 256>>>(W_c1, W_c2, p_Wd1, p_Wd2);

    // B: trk MLP + U2 (bias-free; bc2 added in convs)
    trk_kernel<<<G * 64 / 128, 256, smem_b>>>(
        x_trk, W_trk1, b_trk1, W_trk2, b_trk2, p_Wd2, p_trk, p_U2);

    // merged convs + head
    convs_kernel<<<G, 512, smem_m>>>(
        p_trk, x_sv,
        W_sv1, b_sv1, W_sv2, b_sv2,
        p_Wd1, b_c1, W_c1 + 16384,
        p_U2, W_c2 + 16384, b_c2,
        W_o1, b_o1, W_o2, b_o2, W_o3, b_o3, W_o4, b_o4,
        out, out_size);
}

// round 16
// speedup vs baseline: 1.0300x; 1.0300x over previous
#include <cuda_runtime.h>
#include <math.h>
#include <float.h>

#define G    1024
#define KNN  8

typedef unsigned long long u64;

// ---------------- scratch (static device globals: no allocation) ----------------
__device__ float g_trk[G*64*128];
__device__ float g_U2 [G*64*128];
__device__ float g_f1 [G*64*128];

__device__ __forceinline__ float eluf(float x) { return x > 0.f ? x : expm1f(x); }

// ---- packed f32x2 helpers ----
__device__ __forceinline__ u64 splat2(float a) {
    u64 r; asm("mov.b64 %0, {%1, %1};" : "=l"(r) : "f"(a)); return r;
}
__device__ __forceinline__ u64 pack2f(float x, float y) {
    u64 r; asm("mov.b64 %0, {%1, %2};" : "=l"(r) : "f"(x), "f"(y)); return r;
}
__device__ __forceinline__ void ffma2(u64& c, u64 a, u64 b) {
    asm("fma.rn.f32x2 %0, %1, %2, %0;" : "+l"(c) : "l"(a), "l"(b));
}
__device__ __forceinline__ float2 unpack2(u64 v) {
    float2 f; asm("mov.b64 {%0, %1}, %2;" : "=f"(f.x), "=f"(f.y) : "l"(v)); return f;
}
__device__ __forceinline__ void prefetchL2(const void* p) {
    asm volatile("prefetch.global.L2 [%0];" :: "l"(p));
}

// ---- 32x128 weight chunk staging (LDG->STS), 256 threads ----
// DIFF=false: plain copy of W[kc]; DIFF=true: W_top[kc] - W_bot[kc] of 256x128 W
template<bool DIFF>
__device__ __forceinline__ void stage_chunk(float* dst, const float* __restrict__ W,
                                            int kc, int tid)
{
    #pragma unroll
    for (int e = 0; e < 4; e++) {
        int i4 = tid + e * 256;
        float4 w = ((const float4*)W)[kc * 1024 + i4];
        if (DIFF) {
            float4 w2 = ((const float4*)W)[4096 + kc * 1024 + i4];
            w.x -= w2.x; w.y -= w2.y; w.z -= w2.z; w.w -= w2.w;
        }
        ((float4*)dst)[i4] = w;
    }
}

// ---- GEMM core over one 32-k chunk, 256 threads, 8x8 microtile (trk kernel) ----
__device__ __forceinline__ void zero_acc8(u64 acc[8][4]) {
    #pragma unroll
    for (int i = 0; i < 8; i++)
        #pragma unroll
        for (int j = 0; j < 4; j++) acc[i][j] = 0ull;
}
__device__ __forceinline__ void gemm_chunk(const float* __restrict__ Hs,
                                           const float* __restrict__ Ws,
                                           u64 acc[8][4], int tx, int ty)
{
    #pragma unroll 4
    for (int kk = 0; kk < 32; kk++) {
        const float* arow = &Hs[kk * 132 + ty * 8];
        float4 a0 = *(const float4*)arow;
        float4 a1 = *(const float4*)(arow + 4);
        const u64* br = (const u64*)&Ws[kk * 128];
        u64 b0 = br[tx], b1 = br[tx + 16], b2 = br[tx + 32], b3 = br[tx + 48];
        u64 s;
        s = splat2(a0.x); ffma2(acc[0][0],s,b0); ffma2(acc[0][1],s,b1); ffma2(acc[0][2],s,b2); ffma2(acc[0][3],s,b3);
        s = splat2(a0.y); ffma2(acc[1][0],s,b0); ffma2(acc[1][1],s,b1); ffma2(acc[1][2],s,b2); ffma2(acc[1][3],s,b3);
        s = splat2(a0.z); ffma2(acc[2][0],s,b0); ffma2(acc[2][1],s,b1); ffma2(acc[2][2],s,b2); ffma2(acc[2][3],s,b3);
        s = splat2(a0.w); ffma2(acc[3][0],s,b0); ffma2(acc[3][1],s,b1); ffma2(acc[3][2],s,b2); ffma2(acc[3][3],s,b3);
        s = splat2(a1.x); ffma2(acc[4][0],s,b0); ffma2(acc[4][1],s,b1); ffma2(acc[4][2],s,b2); ffma2(acc[4][3],s,b3);
        s = splat2(a1.y); ffma2(acc[5][0],s,b0); ffma2(acc[5][1],s,b1); ffma2(acc[5][2],s,b2); ffma2(acc[5][3],s,b3);
        s = splat2(a1.z); ffma2(acc[6][0],s,b0); ffma2(acc[6][1],s,b1); ffma2(acc[6][2],s,b2); ffma2(acc[6][3],s,b3);
        s = splat2(a1.w); ffma2(acc[7][0],s,b0); ffma2(acc[7][1],s,b1); ffma2(acc[7][2],s,b2); ffma2(acc[7][3],s,b3);
    }
}
template<bool DIFF>
__device__ __forceinline__ void gemm_pass(const float* __restrict__ Hs, float* Wb,
                                          const float* __restrict__ W,
                                          u64 acc[8][4], int tid, int tx, int ty)
{
    stage_chunk<DIFF>(Wb, W, 0, tid);
    __syncthreads();
    #pragma unroll
    for (int kc = 0; kc < 4; kc++) {
        if (kc < 3) stage_chunk<DIFF>(Wb + ((kc + 1) & 1) * 4096, W, kc + 1, tid);
        gemm_chunk(Hs + kc * 32 * 132, Wb + (kc & 1) * 4096, acc, tx, ty);
        __syncthreads();
    }
}
__device__ __forceinline__ void store256w(const u64 acc[8][4], float* __restrict__ C,
                                          size_t row0, int tx, int ty)
{
    #pragma unroll
    for (int ii = 0; ii < 8; ii++) {
        size_t r = row0 + ty * 8 + ii;
        #pragma unroll
        for (int j = 0; j < 4; j++) {
            float2 p = unpack2(acc[ii][j]);
            *(float2*)&C[r * 128 + tx * 2 + j * 32] = p;
        }
    }
}

// =====================================================================
// trk node kernel: layer1 -> feats -> trkF + U2 = feats @ (Wc2t - Wc2b)
// =====================================================================
__global__ __launch_bounds__(256, 2)
void trk_kernel(const float* __restrict__ X,
                const float* __restrict__ W1, const float* __restrict__ b1,
                const float* __restrict__ W2, const float* __restrict__ b2,
                const float* __restrict__ Wc2,
                float* __restrict__ Yf, float* __restrict__ Yu2)
{
    extern __shared__ float sm[];
    float* Hs  = sm;                    // 128*132
    float* Wb  = Hs + 16896;            // 2*4096
    float* Xin = Wb + 8192;             // 1024
    float* W1s = Xin + 1024;            // 1024
    float* b1s = W1s + 1024;            // 128
    const int tid = threadIdx.x;
    const int tx = tid & 15, ty = tid >> 4;
    const size_t row0 = (size_t)blockIdx.x * 128;

    for (int t = tid; t < 1024; t += 256) Xin[t] = X[row0 * 8 + t];
    for (int t = tid; t < 1024; t += 256) W1s[t] = W1[t];
    if (tid < 128) b1s[tid] = b1[tid];
    __syncthreads();

    {
        int r = tid >> 1, ch = (tid & 1) * 64;
        float xr[8];
        #pragma unroll
        for (int d = 0; d < 8; d++) xr[d] = Xin[r * 8 + d];
        #pragma unroll 4
        for (int cc = 0; cc < 64; cc++) {
            int c = ch + cc;
            float a = b1s[c];
            #pragma unroll
            for (int d = 0; d < 8; d++) a = fmaf(xr[d], W1s[d * 128 + c], a);
            Hs[c * 132 + r] = eluf(a);
        }
    }

    u64 acc[8][4];
    zero_acc8(acc);
    gemm_pass<false>(Hs, Wb, W2, acc, tid, tx, ty);

    {
        float2 bv[4];
        #pragma unroll
        for (int j = 0; j < 4; j++) bv[j] = *(const float2*)&b2[tx * 2 + j * 32];
        #pragma unroll
        for (int ii = 0; ii < 8; ii++) {
            int rr = ty * 8 + ii;
            #pragma unroll
            for (int j = 0; j < 4; j++) {
                float2 p = unpack2(acc[ii][j]);
                float va = fmaxf(p.x + bv[j].x, 0.f);
                float vb = fmaxf(p.y + bv[j].y, 0.f);
                int c = tx * 2 + j * 32;
                float2 o = {va, vb};
                *(float2*)&Yf[(row0 + rr) * 128 + c] = o;
                Hs[c * 132 + rr]       = va;
                Hs[(c + 1) * 132 + rr] = vb;
            }
        }
    }
    __syncthreads();

    zero_acc8(acc);
    gemm_pass<true>(Hs, Wb, Wc2, acc, tid, tx, ty);
    store256w(acc, Yu2, row0, tx, ty);
}

// =====================================================================
// conv1 (fused sv MLP + V1 + U1), pad 132, float4-vectorized k loops.
// Score buffer aliases weight-chunk buffer (disjoint lifetimes).
// 256 threads/graph, ~70KB smem -> 3 blocks/SM.
// =====================================================================
__global__ __launch_bounds__(256, 3)
void conv1_fused(const float* __restrict__ trkF, const float* __restrict__ x_sv,
                 const float* __restrict__ Wsv1, const float* __restrict__ bsv1,
                 const float* __restrict__ Wsv2, const float* __restrict__ bsv2,
                 const float* __restrict__ Wc1,  const float* __restrict__ bc1g,
                 float* __restrict__ f1out)
{
    extern __shared__ float sm[];
    float* dsh  = sm;                  // 64*132 = 8448 trk
    float* ssh  = dsh + 8448;          // 16*132 = 2112 sv feats
    float* vsh  = ssh + 2112;          // 2112 hidden, then V1
    float* Wbuf = vsh + 2112;          // 4096 weight chunk
    float* sc   = Wbuf;                // ALIAS: scores live between svL2 and U1
    float* sn2  = Wbuf + 4096;         // 16
    float* S    = sn2 + 16;            // 672 smalls
    int*  idxs  = (int*)(S + 672);     // 512 ints

    float* xsv = S;          // 32
    float* w1  = S + 32;     // 256
    float* b1  = S + 288;    // 128
    float* b2  = S + 416;    // 128
    float* bc1 = S + 544;    // 128

    const int tid = threadIdx.x;
    const int tx = tid & 15, ty = tid >> 4;       // ty: 0..15
    const int lane = tid & 31, wid = tid >> 5;
    const int g = blockIdx.x;
    const float* dg = trkF + (size_t)g * 64 * 128;
    const float* Wbot1 = Wc1 + 16384;

    for (int t = tid; t < 64 * 128; t += 256)
        dsh[(t >> 7) * 132 + (t & 127)] = dg[t];
    if (tid < 32) xsv[tid] = x_sv[g * 32 + tid];
    w1[tid] = Wsv1[tid];
    if (tid < 128) { b1[tid] = bsv1[tid]; b2[tid] = bsv2[tid]; bc1[tid] = bc1g[tid]; }
    __syncthreads();

    // sv layer1 -> vsh (16 x 128, ld 132)
    {
        float x0 = xsv[ty * 2], x1 = xsv[ty * 2 + 1];
        #pragma unroll
        for (int j = 0; j < 4; j++) {
            int c = 2 * tx + 32 * j;
            vsh[ty * 132 + c]     = eluf(b1[c]     + x0 * w1[c]     + x1 * w1[128 + c]);
            vsh[ty * 132 + c + 1] = eluf(b1[c + 1] + x0 * w1[c + 1] + x1 * w1[128 + c + 1]);
        }
    }
    __syncthreads();

    // sv layer2 (streamed Wsv2) -> ssh = relu(...)
    {
        u64 a[4] = {0ull, 0ull, 0ull, 0ull};
        for (int kc = 0; kc < 4; kc++) {
            stage_chunk<false>(Wbuf, Wsv2, kc, tid);
            __syncthreads();
            #pragma unroll 2
            for (int k4 = 0; k4 < 32; k4 += 4) {
                float4 sv4 = *(const float4*)&vsh[ty * 132 + kc * 32 + k4];
                #pragma unroll
                for (int q = 0; q < 4; q++) {
                    float el = (q == 0) ? sv4.x : (q == 1) ? sv4.y : (q == 2) ? sv4.z : sv4.w;
                    u64 s = splat2(el);
                    const u64* br = (const u64*)&Wbuf[(k4 + q) * 128];
                    ffma2(a[0], s, br[tx]);      ffma2(a[1], s, br[tx + 16]);
                    ffma2(a[2], s, br[tx + 32]); ffma2(a[3], s, br[tx + 48]);
                }
            }
            __syncthreads();
        }
        #pragma unroll
        for (int j = 0; j < 4; j++) {
            float2 p = unpack2(a[j]);
            int c = 2 * tx + 32 * j;
            ssh[ty * 132 + c]     = fmaxf(p.x + b2[c],     0.f);
            ssh[ty * 132 + c + 1] = fmaxf(p.y + b2[c + 1], 0.f);
        }
    }
    __syncthreads();

    // sv squared norms
    #pragma unroll
    for (int q = 0; q < 2; q++) {
        int row = wid * 2 + q;
        const float* rp = &ssh[row * 132];
        float e0 = rp[lane], e1 = rp[32 + lane], e2 = rp[64 + lane], e3 = rp[96 + lane];
        float s = e0*e0 + e1*e1 + e2*e2 + e3*e3;
        #pragma unroll
        for (int off = 16; off > 0; off >>= 1) s += __shfl_xor_sync(~0u, s, off);
        if (lane == 0) sn2[row] = s;
    }
    __syncthreads();

    // scores (float4-vectorized): i = tid>>2, jj = tid&3 -> j = jj + 4m
    {
        int i = tid >> 2, jj = tid & 3;
        u64 a[4] = {0ull, 0ull, 0ull, 0ull};
        #pragma unroll 4
        for (int k4 = 0; k4 < 128; k4 += 4) {
            float4 av = *(const float4*)&dsh[i * 132 + k4];
            u64 a01 = pack2f(av.x, av.y), a23 = pack2f(av.z, av.w);
            #pragma unroll
            for (int m = 0; m < 4; m++) {
                float4 bv = *(const float4*)&ssh[(jj + 4 * m) * 132 + k4];
                ffma2(a[m], a01, pack2f(bv.x, bv.y));
                ffma2(a[m], a23, pack2f(bv.z, bv.w));
            }
        }
        #pragma unroll
        for (int m = 0; m < 4; m++) {
            float2 p = unpack2(a[m]);
            int j = jj + 4 * m;
            sc[i * 17 + j] = sn2[j] - 2.f * (p.x + p.y);
        }
    }
    __syncthreads();

    // warp-parallel top-8 (tie -> lowest index)
    #pragma unroll
    for (int q = 0; q < 8; q++) {
        int row = wid * 8 + q;
        float mv = (lane < 16) ? sc[row * 17 + lane] : FLT_MAX;
        #pragma unroll
        for (int n = 0; n < KNN; n++) {
            float cv = mv; int ci = lane;
            #pragma unroll
            for (int off = 16; off > 0; off >>= 1) {
                float ov = __shfl_xor_sync(~0u, cv, off);
                int   oi = __shfl_xor_sync(~0u, ci, off);
                if (ov < cv || (ov == cv && oi < ci)) { cv = ov; ci = oi; }
            }
            if (lane == 0) idxs[row * 8 + n] = ci;
            if (lane == ci) mv = FLT_MAX;
        }
    }
    __syncthreads();   // scores dead -> Wbuf reusable

    // U1 = trk @ (Wc1_top - Wc1_bot) -> registers
    u64 accU[4][4];
    #pragma unroll
    for (int i = 0; i < 4; i++) { accU[i][0]=0; accU[i][1]=0; accU[i][2]=0; accU[i][3]=0; }
    for (int kc = 0; kc < 4; kc++) {
        stage_chunk<true>(Wbuf, Wc1, kc, tid);
        __syncthreads();
        #pragma unroll 2
        for (int k4 = 0; k4 < 32; k4 += 4) {
            float4 arow[4];
            #pragma unroll
            for (int ii = 0; ii < 4; ii++)
                arow[ii] = *(const float4*)&dsh[(ty * 4 + ii) * 132 + kc * 32 + k4];
            #pragma unroll
            for (int q = 0; q < 4; q++) {
                const u64* br = (const u64*)&Wbuf[(k4 + q) * 128];
                u64 b0 = br[tx], b1v = br[tx + 16], b2v = br[tx + 32], b3v = br[tx + 48];
                #pragma unroll
                for (int ii = 0; ii < 4; ii++) {
                    float el = (q == 0) ? arow[ii].x : (q == 1) ? arow[ii].y
                             : (q == 2) ? arow[ii].z : arow[ii].w;
                    u64 s = splat2(el);
                    ffma2(accU[ii][0], s, b0);  ffma2(accU[ii][1], s, b1v);
                    ffma2(accU[ii][2], s, b2v); ffma2(accU[ii][3], s, b3v);
                }
            }
        }
        __syncthreads();
    }

    // V1 = svfeat @ Wbot1 -> vsh
    {
        u64 a[4] = {0ull, 0ull, 0ull, 0ull};
        for (int kc = 0; kc < 4; kc++) {
            stage_chunk<false>(Wbuf, Wbot1, kc, tid);
            __syncthreads();
            #pragma unroll 2
            for (int k4 = 0; k4 < 32; k4 += 4) {
                float4 sv4 = *(const float4*)&ssh[ty * 132 + kc * 32 + k4];
                #pragma unroll
                for (int q = 0; q < 4; q++) {
                    float el = (q == 0) ? sv4.x : (q == 1) ? sv4.y : (q == 2) ? sv4.z : sv4.w;
                    u64 s = splat2(el);
                    const u64* br = (const u64*)&Wbuf[(k4 + q) * 128];
                    ffma2(a[0], s, br[tx]);      ffma2(a[1], s, br[tx + 16]);
                    ffma2(a[2], s, br[tx + 32]); ffma2(a[3], s, br[tx + 48]);
                }
            }
            __syncthreads();
        }
        #pragma unroll
        for (int j = 0; j < 4; j++) {
            float2 p = unpack2(a[j]);
            *(float2*)&vsh[ty * 132 + 2 * tx + 32 * j] = p;
        }
    }
    __syncthreads();

    // combine: f1 = elu(U1 + bc1 + max_n V1[idx])
    #pragma unroll
    for (int ii = 0; ii < 4; ii++) {
        int row = ty * 4 + ii;
        const int* ip = &idxs[row * 8];
        #pragma unroll
        for (int j = 0; j < 4; j++) {
            int c = 2 * tx + 32 * j;
            float mx = -FLT_MAX, my = -FLT_MAX;
            #pragma unroll
            for (int n = 0; n < KNN; n++) {
                float2 v = *(const float2*)&vsh[ip[n] * 132 + c];
                mx = fmaxf(mx, v.x); my = fmaxf(my, v.y);
            }
            float2 p = unpack2(accU[ii][j]);
            float2 o = { eluf(p.x + bc1[c] + mx), eluf(p.y + bc1[c + 1] + my) };
            *(float2*)&f1out[((size_t)g * 64 + row) * 128 + c] = o;
        }
    }
}

// =====================================================================
// conv2 (fused V2) + head, pad 132, float4-vectorized k loops.
// 512 threads, 2 blocks/SM. Ug prefetched to L2 after topk.
// =====================================================================
__global__ __launch_bounds__(512, 2)
void conv2_head_kernel(const float* __restrict__ trkF, const float* __restrict__ f1,
                       const float* __restrict__ U,    const float* __restrict__ Wbot2,
                       const float* __restrict__ bc2,
                       const float* __restrict__ Wo1, const float* __restrict__ bo1,
                       const float* __restrict__ Wo2, const float* __restrict__ bo2,
                       const float* __restrict__ Wo3, const float* __restrict__ bo3,
                       const float* __restrict__ Wo4, const float* __restrict__ bo4,
                       float* __restrict__ out, int out_size)
{
    extern __shared__ float sm[];
    float* dsh = sm;                    // 64*132 = 8448 (trk; later V2)
    float* ssh = dsh + 8448;            // 8448 (f1)
    float* sc  = ssh + 8448;            // 64*65 = 4160 (scores; later W chunk)
    float* sn2 = sc + 4160;             // 64
    float* colsum = sn2 + 64;           // 512
    float* pooled = colsum + 512;       // 128
    float* h1 = pooled + 128;           // 64
    float* h2 = h1 + 64;                // 32
    float* h3 = h2 + 32;                // 4
    int*  idxs = (int*)(h3 + 4);        // 64*8

    const int g   = blockIdx.x;
    const int tid = threadIdx.x;
    const int wid = tid >> 5, lane = tid & 31;
    const int tx  = tid & 15, ty = tid >> 4;   // ty: 0..31
    const float* dg = trkF + (size_t)g * 64 * 128;
    const float* sg = f1   + (size_t)g * 64 * 128;
    const float* Ug = U    + (size_t)g * 64 * 128;

    for (int t = tid; t < 64 * 128; t += 512) {
        int r = t >> 7, c = t & 127;
        dsh[r * 132 + c] = dg[t];
        ssh[r * 132 + c] = sg[t];
    }
    __syncthreads();

    // f1 squared norms
    #pragma unroll
    for (int q = 0; q < 4; q++) {
        int row = wid * 4 + q;
        const float* rp = &ssh[row * 132];
        float e0 = rp[lane], e1 = rp[32 + lane], e2 = rp[64 + lane], e3 = rp[96 + lane];
        float s = e0*e0 + e1*e1 + e2*e2 + e3*e3;
        #pragma unroll
        for (int off = 16; off > 0; off >>= 1) s += __shfl_xor_sync(~0u, s, off);
        if (lane == 0) sn2[row] = s;
    }
    __syncthreads();

    // scores (float4-vectorized): rows 2ty,2ty+1; cols tx+16jj
    {
        u64 acc[2][4];
        #pragma unroll
        for (int a = 0; a < 2; a++)
            #pragma unroll
            for (int b = 0; b < 4; b++) acc[a][b] = 0ull;
        const int r0 = 2 * ty, r1 = 2 * ty + 1;
        #pragma unroll 4
        for (int k4 = 0; k4 < 128; k4 += 4) {
            float4 av0 = *(const float4*)&dsh[r0 * 132 + k4];
            float4 av1 = *(const float4*)&dsh[r1 * 132 + k4];
            u64 a0p = pack2f(av0.x, av0.y), a0q = pack2f(av0.z, av0.w);
            u64 a1p = pack2f(av1.x, av1.y), a1q = pack2f(av1.z, av1.w);
            #pragma unroll
            for (int jj = 0; jj < 4; jj++) {
                float4 bv = *(const float4*)&ssh[(tx + jj * 16) * 132 + k4];
                u64 bp = pack2f(bv.x, bv.y), bq = pack2f(bv.z, bv.w);
                ffma2(acc[0][jj], a0p, bp); ffma2(acc[0][jj], a0q, bq);
                ffma2(acc[1][jj], a1p, bp); ffma2(acc[1][jj], a1q, bq);
            }
        }
        #pragma unroll
        for (int ii = 0; ii < 2; ii++)
            #pragma unroll
            for (int jj = 0; jj < 4; jj++) {
                float2 p = unpack2(acc[ii][jj]);
                int j = tx + jj * 16;
                sc[(ty * 2 + ii) * 65 + j] = sn2[j] - 2.f * (p.x + p.y);
            }
    }
    __syncthreads();

    // warp-parallel top-8 over 64 candidates (2 per lane)
    #pragma unroll
    for (int q = 0; q < 4; q++) {
        int row = wid * 4 + q;
        float v0 = sc[row * 65 + lane];
        float v1 = sc[row * 65 + 32 + lane];
        #pragma unroll
        for (int n = 0; n < KNN; n++) {
            float cv; int ci;
            if (v1 < v0) { cv = v1; ci = lane + 32; }
            else         { cv = v0; ci = lane; }
            #pragma unroll
            for (int off = 16; off > 0; off >>= 1) {
                float ov = __shfl_xor_sync(~0u, cv, off);
                int   oi = __shfl_xor_sync(~0u, ci, off);
                if (ov < cv || (ov == cv && oi < ci)) { cv = ov; ci = oi; }
            }
            if (lane == 0) idxs[row * 8 + n] = ci;
            if (ci == lane)           v0 = FLT_MAX;
            else if (ci == lane + 32) v1 = FLT_MAX;
        }
    }
    // prefetch Ug tile to L2 (consumed in combine2 after the V2 GEMM)
    if (tid < 256) prefetchL2(Ug + tid * 32);
    __syncthreads();   // topk done: sc free for W chunks; trk (dsh) dead

    // ---- V2 = f1 @ Wbot2, in-block (float4 A loads) ----
    {
        u64 accv[2][4];
        #pragma unroll
        for (int a = 0; a < 2; a++)
            #pragma unroll
            for (int b = 0; b < 4; b++) accv[a][b] = 0ull;
        const int r0 = 2 * ty, r1 = 2 * ty + 1;
        for (int kc = 0; kc < 4; kc++) {
            #pragma unroll
            for (int e = 0; e < 2; e++) {
                int i4 = tid + e * 512;
                ((float4*)sc)[i4] = ((const float4*)Wbot2)[kc * 1024 + i4];
            }
            __syncthreads();
            #pragma unroll 2
            for (int k4 = 0; k4 < 32; k4 += 4) {
                float4 s0v = *(const float4*)&ssh[r0 * 132 + kc * 32 + k4];
                float4 s1v = *(const float4*)&ssh[r1 * 132 + kc * 32 + k4];
                #pragma unroll
                for (int q = 0; q < 4; q++) {
                    float e0 = (q == 0) ? s0v.x : (q == 1) ? s0v.y : (q == 2) ? s0v.z : s0v.w;
                    float e1 = (q == 0) ? s1v.x : (q == 1) ? s1v.y : (q == 2) ? s1v.z : s1v.w;
                    u64 s0 = splat2(e0), s1 = splat2(e1);
                    const u64* br = (const u64*)&sc[(k4 + q) * 128];
                    u64 b0 = br[tx], b1 = br[tx + 16], b2 = br[tx + 32], b3 = br[tx + 48];
                    ffma2(accv[0][0],s0,b0); ffma2(accv[0][1],s0,b1); ffma2(accv[0][2],s0,b2); ffma2(accv[0][3],s0,b3);
                    ffma2(accv[1][0],s1,b0); ffma2(accv[1][1],s1,b1); ffma2(accv[1][2],s1,b2); ffma2(accv[1][3],s1,b3);
                }
            }
            __syncthreads();
        }
        #pragma unroll
        for (int ii = 0; ii < 2; ii++) {
            int r = 2 * ty + ii;
            #pragma unroll
            for (int j = 0; j < 4; j++) {
                float2 p = unpack2(accv[ii][j]);
                *(float2*)&dsh[r * 132 + 2 * tx + 32 * j] = p;
            }
        }
    }
    __syncthreads();

    // combine: elu(U + bc2 + max_n V2[idx]) + column sums
    {
        int c = tid & 127, ih = tid >> 7;
        float bc = bc2[c];
        float csum = 0.f;
        #pragma unroll 4
        for (int i0 = 0; i0 < 64; i0 += 4) {
            int i = i0 + ih;
            const int* ip = &idxs[i * 8];
            float vmax = -FLT_MAX;
            #pragma unroll
            for (int n = 0; n < KNN; n++) vmax = fmaxf(vmax, dsh[ip[n] * 132 + c]);
            csum += eluf(Ug[i * 128 + c] + bc + vmax);
        }
        colsum[ih * 128 + c] = csum;
    }
    __syncthreads();
    if (tid < 128)
        pooled[tid] = (colsum[tid] + colsum[128 + tid] + colsum[256 + tid] + colsum[384 + tid]) * (1.f / 64.f);
    __syncthreads();
    if (tid < 64) {
        float a = bo1[tid];
        #pragma unroll 8
        for (int d = 0; d < 128; d++) a += pooled[d] * Wo1[d * 64 + tid];
        h1[tid] = eluf(a);
    }
    __syncthreads();
    if (tid < 32) {
        float a = bo2[tid];
        #pragma unroll 8
        for (int d = 0; d < 64; d++) a += h1[d] * Wo2[d * 32 + tid];
        h2[tid] = eluf(a);
    }
    __syncthreads();
    if (tid < 4) {
        float a = bo3[tid];
        #pragma unroll
        for (int d = 0; d < 32; d++) a += h2[d] * Wo3[d * 4 + tid];
        h3[tid] = eluf(a);
    }
    __syncthreads();
    if (tid == 0) {
        float a = bo4[0];
        #pragma unroll
        for (int d = 0; d < 4; d++) a += h3[d] * Wo4[d];
        out[g] = a;
        if (out_size >= 2 * G) out[G + g] = (float)g;
    }
}

// ---------------- launch ----------------
extern "C" void kernel_launch(void* const* d_in, const int* in_sizes, int n_in,
                              void* d_out, int out_size)
{
    const float* x_sv   = (const float*)d_in[0];
    const float* x_trk  = (const float*)d_in[1];
    const float* W_sv1  = (const float*)d_in[2];
    const float* b_sv1  = (const float*)d_in[3];
    const float* W_sv2  = (const float*)d_in[4];
    const float* b_sv2  = (const float*)d_in[5];
    const float* W_trk1 = (const float*)d_in[6];
    const float* b_trk1 = (const float*)d_in[7];
    const float* W_trk2 = (const float*)d_in[8];
    const float* b_trk2 = (const float*)d_in[9];
    const float* W_c1   = (const float*)d_in[10];
    const float* b_c1   = (const float*)d_in[11];
    const float* W_c2   = (const float*)d_in[12];
    const float* b_c2   = (const float*)d_in[13];
    const float* W_o1   = (const float*)d_in[14];
    const float* b_o1   = (const float*)d_in[15];
    const float* W_o2   = (const float*)d_in[16];
    const float* b_o2   = (const float*)d_in[17];
    const float* W_o3   = (const float*)d_in[18];
    const float* b_o3   = (const float*)d_in[19];
    const float* W_o4   = (const float*)d_in[20];
    const float* b_o4   = (const float*)d_in[21];
    float* out = (float*)d_out;

    float *p_trk, *p_U2, *p_f1;
    cudaGetSymbolAddress((void**)&p_trk, g_trk);
    cudaGetSymbolAddress((void**)&p_U2,  g_U2);
    cudaGetSymbolAddress((void**)&p_f1,  g_f1);

    const int smem_b  = (16896 + 8192 + 1024 + 1024 + 128) * 4;
    const int smem_c1 = (8448 + 2112 + 2112 + 4096 + 16 + 672) * 4 + 512 * 4;
    const int smem_d  = (8448 + 8448 + 4160 + 64 + 512 + 128 + 64 + 32 + 4) * 4 + 512 * 4;

    (void)cudaFuncSetAttribute(trk_kernel,        cudaFuncAttributeMaxDynamicSharedMemorySize, smem_b);
    (void)cudaFuncSetAttribute(conv1_fused,       cudaFuncAttributeMaxDynamicSharedMemorySize, smem_c1);
    (void)cudaFuncSetAttribute(conv2_head_kernel, cudaFuncAttributeMaxDynamicSharedMemorySize, smem_d);

    // B: trk MLP + U2 (diff weights computed in staging; bc2 added in conv2)
    trk_kernel<<<G * 64 / 128, 256, smem_b>>>(
        x_trk, W_trk1, b_trk1, W_trk2, b_trk2, W_c2, p_trk, p_U2);

    // C: conv1 fully fused -> f1
    conv1_fused<<<G, 256, smem_c1>>>(
        p_trk, x_sv, W_sv1, b_sv1, W_sv2, b_sv2,
        W_c1, b_c1, p_f1);

    // D: conv2 (+ fused V2) + head
    conv2_head_kernel<<<G, 512, smem_d>>>(p_trk, p_f1, p_U2,
        W_c2 + 16384, b_c2,
        W_o1, b_o1, W_o2, b_o2, W_o3, b_o3, W_o4, b_o4, out, out_size);
}